// round 15
// baseline (speedup 1.0000x reference)
#include <cuda_runtime.h>
#include <cuda_fp16.h>
#include <math.h>
#include <stdint.h>

#define BB 8
#define SS 1024
#define DD 1024
#define HH 16
#define HD 64

// Scratch (device globals: allocation-free rule workaround)
__device__ __half   g_q[(size_t)BB * SS * DD];
__device__ __half   g_k[(size_t)BB * SS * DD];
__device__ __half   g_v[(size_t)BB * SS * DD];
__device__ __half   g_aoh[(size_t)BB * SS * DD];
__device__ uint32_t g_maskw[(size_t)BB * SS * (SS / 32)];
__device__ __half   g_synh[(size_t)HH * SS * SS];
__device__ __half   g_qin[(size_t)BB * SS * DD];
__device__ __half   g_kin[(size_t)BB * SS * DD];
__device__ __half   g_vin[(size_t)BB * SS * DD];
__device__ __half   g_wq[(size_t)DD * DD];
__device__ __half   g_wk[(size_t)DD * DD];
__device__ __half   g_wv[(size_t)DD * DD];
__device__ __half   g_wo[(size_t)DD * DD];

__device__ __forceinline__ uint32_t smem_u32(const void* p) {
    uint32_t a;
    asm("{ .reg .u64 t; cvta.to.shared.u64 t, %1; cvt.u32.u64 %0, t; }" : "=r"(a) : "l"(p));
    return a;
}
__device__ __forceinline__ uint32_t f2h2(float lo, float hi) {
    __half2 h = __floats2half2_rn(lo, hi);
    return *(uint32_t*)&h;
}
__device__ __forceinline__ uint2 f4h(float4 t) {
    return make_uint2(f2h2(t.x, t.y), f2h2(t.z, t.w));
}

__device__ __forceinline__ void mma16(float* d, const uint32_t* a, const uint32_t* b) {
    asm volatile(
        "mma.sync.aligned.m16n8k16.row.col.f32.f16.f16.f32 "
        "{%0,%1,%2,%3}, {%4,%5,%6,%7}, {%8,%9}, {%0,%1,%2,%3};"
        : "+f"(d[0]), "+f"(d[1]), "+f"(d[2]), "+f"(d[3])
        : "r"(a[0]), "r"(a[1]), "r"(a[2]), "r"(a[3]), "r"(b[0]), "r"(b[1]));
}
__device__ __forceinline__ void ldsm_x4(uint32_t* r, uint32_t addr) {
    asm volatile("ldmatrix.sync.aligned.m8n8.x4.shared.b16 {%0,%1,%2,%3}, [%4];"
                 : "=r"(r[0]), "=r"(r[1]), "=r"(r[2]), "=r"(r[3]) : "r"(addr));
}
__device__ __forceinline__ void ldsm_x4t(uint32_t* r, uint32_t addr) {
    asm volatile("ldmatrix.sync.aligned.m8n8.x4.trans.shared.b16 {%0,%1,%2,%3}, [%4];"
                 : "=r"(r[0]), "=r"(r[1]), "=r"(r[2]), "=r"(r[3]) : "r"(addr));
}
__device__ __forceinline__ void cpa16(uint32_t dst, const void* src) {
    asm volatile("cp.async.cg.shared.global [%0], [%1], 16;"
                 :: "r"(dst), "l"(src) : "memory");
}
__device__ __forceinline__ void cpa_commit() {
    asm volatile("cp.async.commit_group;" ::: "memory");
}
template <int N> __device__ __forceinline__ void cpa_wait() {
    asm volatile("cp.async.wait_group %0;" :: "n"(N) : "memory");
}

// ---------------------------------------------------------------------------
// Prep (R11 exact): pack_mask + conv_all (2 launches)
// ---------------------------------------------------------------------------
__global__ __launch_bounds__(256) void pack_mask(const int* __restrict__ mask,
                                                 uint32_t* __restrict__ mw)
{
    const size_t w = (size_t)blockIdx.x * 256 + threadIdx.x;
    const int4* p = (const int4*)(mask + w * 32);
    uint32_t bits = 0;
#pragma unroll
    for (int i = 0; i < 8; i++) {
        int4 v = p[i];
        bits |= (v.x != 0 ? 1u : 0u) << (i * 4 + 0);
        bits |= (v.y != 0 ? 1u : 0u) << (i * 4 + 1);
        bits |= (v.z != 0 ? 1u : 0u) << (i * 4 + 2);
        bits |= (v.w != 0 ? 1u : 0u) << (i * 4 + 3);
    }
    mw[w] = bits;
}

__global__ __launch_bounds__(256) void conv_all(
    const float* __restrict__ syn,
    const float* __restrict__ q, const float* __restrict__ k, const float* __restrict__ v,
    const float* __restrict__ wq, const float* __restrict__ wk,
    const float* __restrict__ wv, const float* __restrict__ wo,
    const float* __restrict__ alpha_param,
    __half* __restrict__ osyn,
    __half* __restrict__ oq, __half* __restrict__ ok, __half* __restrict__ ov,
    __half* __restrict__ owq, __half* __restrict__ owk,
    __half* __restrict__ owv, __half* __restrict__ owo)
{
    const int blk = blockIdx.x;
    const float* src;
    __half* dst;
    size_t off;
    bool scale = false;
    if (blk < 4096)       { src = syn; dst = osyn; off = (size_t)blk * 1024; scale = true; }
    else if (blk < 6144)  { src = q;   dst = oq;   off = (size_t)(blk - 4096) * 1024; }
    else if (blk < 8192)  { src = k;   dst = ok;   off = (size_t)(blk - 6144) * 1024; }
    else if (blk < 10240) { src = v;   dst = ov;   off = (size_t)(blk - 8192) * 1024; }
    else if (blk < 10496) { src = wq;  dst = owq;  off = (size_t)(blk - 10240) * 1024; }
    else if (blk < 10752) { src = wk;  dst = owk;  off = (size_t)(blk - 10496) * 1024; }
    else if (blk < 11008) { src = wv;  dst = owv;  off = (size_t)(blk - 10752) * 1024; }
    else                  { src = wo;  dst = owo;  off = (size_t)(blk - 11008) * 1024; }

    float mult = 1.0f;
    if (scale) {
        float alpha = 1.0f / (1.0f + __expf(-alpha_param[0]));
        mult = (1.0f - alpha) * 1.4426950408889634f;
    }

    const size_t base = off + threadIdx.x;
    float4 t[4];
#pragma unroll
    for (int j = 0; j < 4; j++) t[j] = *(const float4*)(src + (base + j * 256) * 4);
#pragma unroll
    for (int j = 0; j < 4; j++) {
        t[j].x *= mult; t[j].y *= mult; t[j].z *= mult; t[j].w *= mult;
        *(uint2*)(dst + (base + j * 256) * 4) = f4h(t[j]);
    }
}

// ---------------------------------------------------------------------------
// GEMM core: fp16 in, 2-stage cp.async, k-slice 64 (16 barriers total).
// Block 128x128, 8 warps (2x4), warp tile 64x32, 2 CTAs/SM.
// smem per stage: A 128x72h + W 128x72h = 36864B; 2 stages = 73728B dynamic.
// Fill: 128 rows x 8 chunks(16B) per matrix = 1024 chunks; 4/thread/matrix.
// ---------------------------------------------------------------------------
#define GSTRIDE 72
#define GSTAGE_H (128 * GSTRIDE)
#define GEMM_SMEM (2 * 2 * GSTAGE_H * 2)   // 73728 bytes

__device__ __forceinline__ void gemm_core(
    const __half* __restrict__ A, const __half* __restrict__ W,
    const float* __restrict__ bias, void* __restrict__ Cv, int head_layout,
    __half* smh, int bx, int by)
{
    const int tid  = threadIdx.x;
    const int lane = tid & 31;
    const int warp = tid >> 5;
    const int wm   = warp >> 2;
    const int wn   = warp & 3;
    const int lr   = lane >> 2;
    const int lc   = lane & 3;
    const int aRow = lane & 15;
    const int aK   = (lane >> 4) * 8;
    const int bRow16 = (lane >> 4) * 8 + (lane & 7);
    const int bCol   = ((lane >> 3) & 1) * 8;

    // fill geometry: row = tid>>1 (0..127), col base = (tid&1)*32 halves,
    // 4 chunks of 8 halves each per matrix.
    const int fr  = tid >> 1;
    const int fcb = (tid & 1) * 32;

    const __half* Ab = A + (size_t)(by * 128) * DD;
    const __half* Wb = W + (size_t)(bx * 128) * DD;

    const uint32_t base = smem_u32(smh);
    uint32_t sA[2], sW[2];
#pragma unroll
    for (int s = 0; s < 2; s++) {
        sA[s] = base + (uint32_t)(s * 2 * GSTAGE_H) * 2;
        sW[s] = sA[s] + (uint32_t)GSTAGE_H * 2;
    }

    float acc[4][4][4];
#pragma unroll
    for (int mt = 0; mt < 4; mt++)
#pragma unroll
        for (int nt = 0; nt < 4; nt++)
#pragma unroll
            for (int r = 0; r < 4; r++) acc[mt][nt][r] = 0.0f;

#define ISSUE(slice) { \
        int s_ = (slice) & 1; \
        const __half* aRowP = Ab + (size_t)fr * DD + (slice) * 64 + fcb; \
        const __half* wRowP = Wb + (size_t)fr * DD + (slice) * 64 + fcb; \
        uint32_t aDst = sA[s_] + (uint32_t)(fr * GSTRIDE + fcb) * 2; \
        uint32_t wDst = sW[s_] + (uint32_t)(fr * GSTRIDE + fcb) * 2; \
        cpa16(aDst,      aRowP);      cpa16(aDst + 16, aRowP + 8); \
        cpa16(aDst + 32, aRowP + 16); cpa16(aDst + 48, aRowP + 24); \
        cpa16(wDst,      wRowP);      cpa16(wDst + 16, wRowP + 8); \
        cpa16(wDst + 32, wRowP + 16); cpa16(wDst + 48, wRowP + 24); \
        cpa_commit(); }

    ISSUE(0);

    for (int kt = 0; kt < 16; kt++) {           // 16 slices of k=64
        cpa_wait<0>();
        __syncthreads();                         // all warps done with buf^1
        if (kt + 1 < 16) ISSUE(kt + 1);

        const int s = kt & 1;
#pragma unroll
        for (int ks = 0; ks < 4; ks++) {
            uint32_t af[4][4], bf[4][2];
#pragma unroll
            for (int mt = 0; mt < 4; mt++)
                ldsm_x4(af[mt], sA[s] +
                        ((uint32_t)((wm * 64 + mt * 16 + aRow) * GSTRIDE + ks * 16 + aK) << 1));
#pragma unroll
            for (int p = 0; p < 2; p++) {
                uint32_t t4[4];
                ldsm_x4(t4, sW[s] +
                        ((uint32_t)((wn * 32 + p * 16 + bRow16) * GSTRIDE + ks * 16 + bCol) << 1));
                bf[p * 2][0] = t4[0]; bf[p * 2][1] = t4[1];
                bf[p * 2 + 1][0] = t4[2]; bf[p * 2 + 1][1] = t4[3];
            }
#pragma unroll
            for (int mt = 0; mt < 4; mt++)
#pragma unroll
                for (int nt = 0; nt < 4; nt++)
                    mma16(acc[mt][nt], af[mt], bf[nt]);
        }
    }
#undef ISSUE

#pragma unroll
    for (int mt = 0; mt < 4; mt++) {
#pragma unroll
        for (int nt = 0; nt < 4; nt++) {
            int m0 = by * 128 + wm * 64 + mt * 16 + lr;
            int n0 = bx * 128 + wn * 32 + nt * 8 + 2 * lc;
            float bxv = bias[n0], byv = bias[n0 + 1];
            float v00 = acc[mt][nt][0] + bxv, v01 = acc[mt][nt][1] + byv;
            float v10 = acc[mt][nt][2] + bxv, v11 = acc[mt][nt][3] + byv;
            if (head_layout) {
                __half* C = (__half*)Cv;
                int hI = n0 >> 6, hd = n0 & 63;
                int bI0 = m0 >> 10, sI0 = m0 & 1023;
                int m1 = m0 + 8;
                int bI1 = m1 >> 10, sI1 = m1 & 1023;
                *(uint32_t*)(C + (((size_t)(bI0 * HH + hI) * SS + sI0) * HD + hd)) = f2h2(v00, v01);
                *(uint32_t*)(C + (((size_t)(bI1 * HH + hI) * SS + sI1) * HD + hd)) = f2h2(v10, v11);
            } else {
                float* C = (float*)Cv;
                *(float2*)(C + (size_t)m0 * DD + n0) = make_float2(v00, v01);
                *(float2*)(C + (size_t)(m0 + 8) * DD + n0) = make_float2(v10, v11);
            }
        }
    }
}

__global__ __launch_bounds__(256, 2) void gemm_qkv(
    const __half* __restrict__ qin, const __half* __restrict__ kin,
    const __half* __restrict__ vin,
    const __half* __restrict__ wq, const __half* __restrict__ wk,
    const __half* __restrict__ wv,
    const float* __restrict__ bq, const float* __restrict__ bk,
    const float* __restrict__ bv,
    __half* __restrict__ oq, __half* __restrict__ ok, __half* __restrict__ ov)
{
    extern __shared__ __align__(16) __half smh[];
    const int z = blockIdx.z;
    const __half* A = (z == 0) ? qin : (z == 1) ? kin : vin;
    const __half* W = (z == 0) ? wq  : (z == 1) ? wk  : wv;
    const float* bias = (z == 0) ? bq : (z == 1) ? bk : bv;
    __half* C = (z == 0) ? oq : (z == 1) ? ok : ov;
    gemm_core(A, W, bias, C, 1, smh, blockIdx.x, blockIdx.y);
}

__global__ __launch_bounds__(256, 2) void gemm_o(
    const __half* __restrict__ A, const __half* __restrict__ W,
    const float* __restrict__ bias, float* __restrict__ C)
{
    extern __shared__ __align__(16) __half smh[];
    gemm_core(A, W, bias, C, 0, smh, blockIdx.x, blockIdx.y);
}

// ---------------------------------------------------------------------------
// Flash attention (R11 exact: 2-buffer static, cp.async, x4 LDSM, register P)
// ---------------------------------------------------------------------------
__global__ __launch_bounds__(256, 2) void attn_f16(
    const __half* __restrict__ gq, const __half* __restrict__ gk,
    const __half* __restrict__ gv, const uint32_t* __restrict__ maskw,
    const __half* __restrict__ synh, const float* __restrict__ alpha_param,
    __half* __restrict__ out)
{
    __shared__ __align__(16) __half KV[4][64 * 72];
    const uint32_t KsA[2] = { smem_u32(KV[0]), smem_u32(KV[1]) };
    const uint32_t VsA[2] = { smem_u32(KV[2]), smem_u32(KV[3]) };

    const int tid  = threadIdx.x;
    const int lane = tid & 31;
    const int warp = tid >> 5;
    const int lr   = lane >> 2;
    const int lc   = lane & 3;
    const int aRow = lane & 15;
    const int aK   = (lane >> 4) * 8;
    const int bRow16 = (lane >> 4) * 8 + (lane & 7);
    const int bCol   = ((lane >> 3) & 1) * 8;
    const int vRow   = ((lane >> 3) & 1) * 8 + (lane & 7);
    const int vColH  = (lane >> 4) * 8;
    const int b = blockIdx.y >> 4;
    const int h = blockIdx.y & 15;
    const int qbase = blockIdx.x * 128;
    const int rb = warp * 16;

    const float alpha = 1.0f / (1.0f + __expf(-alpha_param[0]));
    const float sA2   = alpha * 0.125f * 1.4426950408889634f;

    const __half* qptr = gq + ((size_t)(b * HH + h) * SS + qbase) * HD;
    const __half* kptr = gk + (size_t)(b * HH + h) * SS * HD;
    const __half* vptr = gv + (size_t)(b * HH + h) * SS * HD;

    const int c0 = tid * 2;
    const int fr0 = c0 >> 3, fc0 = (c0 & 7) * 8;
    const int fr1 = (c0 + 1) >> 3, fc1 = ((c0 + 1) & 7) * 8;

#define ISSUE_KV(i, buf) { \
        const __half* kp_ = kptr + (size_t)(i) * 64 * HD; \
        const __half* vp_ = vptr + (size_t)(i) * 64 * HD; \
        cpa16(KsA[buf] + (uint32_t)(fr0 * 72 + fc0) * 2, kp_ + (size_t)fr0 * HD + fc0); \
        cpa16(KsA[buf] + (uint32_t)(fr1 * 72 + fc1) * 2, kp_ + (size_t)fr1 * HD + fc1); \
        cpa16(VsA[buf] + (uint32_t)(fr0 * 72 + fc0) * 2, vp_ + (size_t)fr0 * HD + fc0); \
        cpa16(VsA[buf] + (uint32_t)(fr1 * 72 + fc1) * 2, vp_ + (size_t)fr1 * HD + fc1); \
        cpa_commit(); }

    {
        __half* Qstage = KV[0];
#pragma unroll
        for (int i = 0; i < 8; i++) {
            int id = tid + i * 256;
            int r  = id >> 4;
            int c4 = (id & 15) * 4;
            *(uint2*)&Qstage[r * 72 + c4] = *(const uint2*)(qptr + (size_t)r * HD + c4);
        }
    }
    __syncthreads();

    uint32_t qf[4][4];
#pragma unroll
    for (int kk = 0; kk < 4; kk++)
        ldsm_x4(qf[kk], KsA[0] + ((uint32_t)((rb + aRow) * 72 + kk * 16 + aK) << 1));
    __syncthreads();

    ISSUE_KV(0, 0);

    float O[8][4];
#pragma unroll
    for (int nt = 0; nt < 8; nt++)
#pragma unroll
        for (int r = 0; r < 4; r++) O[nt][r] = 0.0f;
    float m0r = -INFINITY, m1r = -INFINITY, l0 = 0.0f, l1 = 0.0f;

    const int qr0 = qbase + rb + lr;
    const int qr1 = qr0 + 8;
    const uint32_t* mw0 = maskw + ((size_t)b * SS + qr0) * 32;
    const uint32_t* mw1 = maskw + ((size_t)b * SS + qr1) * 32;
    const __half* sy0p = synh + ((size_t)h * SS + qr0) * SS;
    const __half* sy1p = synh + ((size_t)h * SS + qr1) * SS;

    int buf = 0;
    for (int it = 0; it < 16; it++) {
        const int kb = it * 64;
        cpa_wait<0>();
        __syncthreads();
        if (it < 15) ISSUE_KV(it + 1, buf ^ 1);

        float sacc[8][4];
#pragma unroll
        for (int nt = 0; nt < 8; nt++)
            sacc[nt][0] = sacc[nt][1] = sacc[nt][2] = sacc[nt][3] = 0.0f;
#pragma unroll
        for (int p = 0; p < 4; p++) {
#pragma unroll
            for (int kk = 0; kk < 4; kk++) {
                uint32_t t4[4];
                ldsm_x4(t4, KsA[buf] +
                        ((uint32_t)((p * 16 + bRow16) * 72 + kk * 16 + bCol) << 1));
                mma16(sacc[p * 2],     qf[kk], t4);
                mma16(sacc[p * 2 + 1], qf[kk], t4 + 2);
            }
        }

        const uint32_t w0a = mw0[kb >> 5], w0b = mw0[(kb >> 5) + 1];
        const uint32_t w1a = mw1[kb >> 5], w1b = mw1[(kb >> 5) + 1];
        float mx0 = -INFINITY, mx1 = -INFINITY;
#pragma unroll
        for (int nt = 0; nt < 8; nt++) {
            const int pos = nt * 8 + 2 * lc;
            const int sh  = pos & 31;
            const uint32_t wr0 = (nt < 4) ? w0a : w0b;
            const uint32_t wr1 = (nt < 4) ? w1a : w1b;
            float2 sy0 = __half22float2(*(const __half2*)(sy0p + kb + pos));
            float2 sy1 = __half22float2(*(const __half2*)(sy1p + kb + pos));
            sacc[nt][0] = ((wr0 >> sh) & 1u)       ? fmaf(sacc[nt][0], sA2, sy0.x) : -1.0e9f;
            sacc[nt][1] = ((wr0 >> (sh + 1)) & 1u) ? fmaf(sacc[nt][1], sA2, sy0.y) : -1.0e9f;
            sacc[nt][2] = ((wr1 >> sh) & 1u)       ? fmaf(sacc[nt][2], sA2, sy1.x) : -1.0e9f;
            sacc[nt][3] = ((wr1 >> (sh + 1)) & 1u) ? fmaf(sacc[nt][3], sA2, sy1.y) : -1.0e9f;
            mx0 = fmaxf(mx0, fmaxf(sacc[nt][0], sacc[nt][1]));
            mx1 = fmaxf(mx1, fmaxf(sacc[nt][2], sacc[nt][3]));
        }
        mx0 = fmaxf(mx0, __shfl_xor_sync(0xffffffffu, mx0, 1));
        mx0 = fmaxf(mx0, __shfl_xor_sync(0xffffffffu, mx0, 2));
        mx1 = fmaxf(mx1, __shfl_xor_sync(0xffffffffu, mx1, 1));
        mx1 = fmaxf(mx1, __shfl_xor_sync(0xffffffffu, mx1, 2));

        float mn0 = fmaxf(m0r, mx0), mn1 = fmaxf(m1r, mx1);
        float sc0 = exp2f(m0r - mn0), sc1 = exp2f(m1r - mn1);
        m0r = mn0; m1r = mn1;

        uint32_t pf[4][4];
        float rs0 = 0.0f, rs1 = 0.0f;
#pragma unroll
        for (int nt = 0; nt < 8; nt++) {
            float p0 = exp2f(sacc[nt][0] - mn0);
            float p1 = exp2f(sacc[nt][1] - mn0);
            float p2 = exp2f(sacc[nt][2] - mn1);
            float p3 = exp2f(sacc[nt][3] - mn1);
            rs0 += p0 + p1;
            rs1 += p2 + p3;
            pf[nt >> 1][(nt & 1) * 2 + 0] = f2h2(p0, p1);
            pf[nt >> 1][(nt & 1) * 2 + 1] = f2h2(p2, p3);
        }
        rs0 += __shfl_xor_sync(0xffffffffu, rs0, 1);
        rs0 += __shfl_xor_sync(0xffffffffu, rs0, 2);
        rs1 += __shfl_xor_sync(0xffffffffu, rs1, 1);
        rs1 += __shfl_xor_sync(0xffffffffu, rs1, 2);
        l0 = l0 * sc0 + rs0;
        l1 = l1 * sc1 + rs1;

#pragma unroll
        for (int nt = 0; nt < 8; nt++) {
            O[nt][0] *= sc0; O[nt][1] *= sc0;
            O[nt][2] *= sc1; O[nt][3] *= sc1;
        }

#pragma unroll
        for (int j = 0; j < 4; j++) {
#pragma unroll
            for (int p = 0; p < 4; p++) {
                uint32_t t4[4];
                ldsm_x4t(t4, VsA[buf] +
                         ((uint32_t)((j * 16 + vRow) * 72 + p * 16 + vColH) << 1));
                mma16(O[p * 2],     pf[j], t4);
                mma16(O[p * 2 + 1], pf[j], t4 + 2);
            }
        }

        buf ^= 1;
    }
#undef ISSUE_KV

    float inv0 = 1.0f / l0, inv1 = 1.0f / l1;
    __half* o0 = out + ((size_t)b * SS + qr0) * DD + h * HD;
    __half* o1 = out + ((size_t)b * SS + qr1) * DD + h * HD;
#pragma unroll
    for (int nt = 0; nt < 8; nt++) {
        int c = nt * 8 + 2 * lc;
        *(uint32_t*)(o0 + c) = f2h2(O[nt][0] * inv0, O[nt][1] * inv0);
        *(uint32_t*)(o1 + c) = f2h2(O[nt][2] * inv1, O[nt][3] * inv1);
    }
}

// ---------------------------------------------------------------------------
extern "C" void kernel_launch(void* const* d_in, const int* in_sizes, int n_in,
                              void* d_out, int out_size)
{
    const float* query  = (const float*)d_in[0];
    const float* key_in = (const float*)d_in[1];
    const float* value  = (const float*)d_in[2];
    const int*   mask   = (const int*)d_in[3];
    const float* Wq = (const float*)d_in[4];
    const float* bq = (const float*)d_in[5];
    const float* Wk = (const float*)d_in[6];
    const float* bk = (const float*)d_in[7];
    const float* Wv = (const float*)d_in[8];
    const float* bv = (const float*)d_in[9];
    const float* Wo = (const float*)d_in[10];
    const float* bo = (const float*)d_in[11];
    const float* syn = (const float*)d_in[12];
    const float* alpha_param = (const float*)d_in[13];
    float* out = (float*)d_out;

    __half *pq, *pk, *pv, *paoh, *psynh, *pqin, *pkin, *pvin, *pwq, *pwk, *pwv, *pwo;
    uint32_t *pmw;
    cudaGetSymbolAddress((void**)&pq, g_q);
    cudaGetSymbolAddress((void**)&pk, g_k);
    cudaGetSymbolAddress((void**)&pv, g_v);
    cudaGetSymbolAddress((void**)&paoh, g_aoh);
    cudaGetSymbolAddress((void**)&pmw, g_maskw);
    cudaGetSymbolAddress((void**)&psynh, g_synh);
    cudaGetSymbolAddress((void**)&pqin, g_qin);
    cudaGetSymbolAddress((void**)&pkin, g_kin);
    cudaGetSymbolAddress((void**)&pvin, g_vin);
    cudaGetSymbolAddress((void**)&pwq, g_wq);
    cudaGetSymbolAddress((void**)&pwk, g_wk);
    cudaGetSymbolAddress((void**)&pwv, g_wv);
    cudaGetSymbolAddress((void**)&pwo, g_wo);

    // Prep: 2 launches (R11 exact)
    pack_mask<<<(BB * SS * (SS / 32)) / 256, 256>>>(mask, pmw);
    conv_all<<<11264, 256>>>(syn, query, key_in, value, Wq, Wk, Wv, Wo,
                             alpha_param,
                             psynh, pqin, pkin, pvin, pwq, pwk, pwv, pwo);

    cudaFuncSetAttribute(gemm_qkv,
                         cudaFuncAttributeMaxDynamicSharedMemorySize, GEMM_SMEM);
    cudaFuncSetAttribute(gemm_o,
                         cudaFuncAttributeMaxDynamicSharedMemorySize, GEMM_SMEM);

    gemm_qkv<<<dim3(DD / 128, (BB * SS) / 128, 3), 256, GEMM_SMEM>>>(
        pqin, pkin, pvin, pwq, pwk, pwv, bq, bk, bv, pq, pk, pv);

    attn_f16<<<dim3(SS / 128, BB * HH), 256>>>(
        pq, pk, pv, pmw, psynh, alpha_param, paoh);

    gemm_o<<<dim3(DD / 128, (BB * SS) / 128), 256, GEMM_SMEM>>>(
        paoh, pwo, bo, out);
}

// round 16
// speedup vs baseline: 1.1271x; 1.1271x over previous
#include <cuda_runtime.h>
#include <cuda_fp16.h>
#include <math.h>
#include <stdint.h>

#define BB 8
#define SS 1024
#define DD 1024
#define HH 16
#define HD 64

// Scratch (device globals: allocation-free rule workaround)
__device__ __half   g_q[(size_t)BB * SS * DD];
__device__ __half   g_k[(size_t)BB * SS * DD];
__device__ __half   g_v[(size_t)BB * SS * DD];
__device__ __half   g_aoh[(size_t)BB * SS * DD];
__device__ uint32_t g_maskw[(size_t)BB * SS * (SS / 32)];
__device__ __half   g_synh[(size_t)HH * SS * SS];
__device__ __half   g_qin[(size_t)BB * SS * DD];
__device__ __half   g_kin[(size_t)BB * SS * DD];
__device__ __half   g_vin[(size_t)BB * SS * DD];
__device__ __half   g_wq[(size_t)DD * DD];
__device__ __half   g_wk[(size_t)DD * DD];
__device__ __half   g_wv[(size_t)DD * DD];
__device__ __half   g_wo[(size_t)DD * DD];

__device__ __forceinline__ uint32_t smem_u32(const void* p) {
    uint32_t a;
    asm("{ .reg .u64 t; cvta.to.shared.u64 t, %1; cvt.u32.u64 %0, t; }" : "=r"(a) : "l"(p));
    return a;
}
__device__ __forceinline__ uint32_t f2h2(float lo, float hi) {
    __half2 h = __floats2half2_rn(lo, hi);
    return *(uint32_t*)&h;
}
__device__ __forceinline__ uint2 f4h(float4 t) {
    return make_uint2(f2h2(t.x, t.y), f2h2(t.z, t.w));
}

__device__ __forceinline__ void mma16(float* d, const uint32_t* a, const uint32_t* b) {
    asm volatile(
        "mma.sync.aligned.m16n8k16.row.col.f32.f16.f16.f32 "
        "{%0,%1,%2,%3}, {%4,%5,%6,%7}, {%8,%9}, {%0,%1,%2,%3};"
        : "+f"(d[0]), "+f"(d[1]), "+f"(d[2]), "+f"(d[3])
        : "r"(a[0]), "r"(a[1]), "r"(a[2]), "r"(a[3]), "r"(b[0]), "r"(b[1]));
}
__device__ __forceinline__ void ldsm_x4(uint32_t* r, uint32_t addr) {
    asm volatile("ldmatrix.sync.aligned.m8n8.x4.shared.b16 {%0,%1,%2,%3}, [%4];"
                 : "=r"(r[0]), "=r"(r[1]), "=r"(r[2]), "=r"(r[3]) : "r"(addr));
}
__device__ __forceinline__ void ldsm_x4t(uint32_t* r, uint32_t addr) {
    asm volatile("ldmatrix.sync.aligned.m8n8.x4.trans.shared.b16 {%0,%1,%2,%3}, [%4];"
                 : "=r"(r[0]), "=r"(r[1]), "=r"(r[2]), "=r"(r[3]) : "r"(addr));
}
__device__ __forceinline__ void cpa16(uint32_t dst, const void* src) {
    asm volatile("cp.async.cg.shared.global [%0], [%1], 16;"
                 :: "r"(dst), "l"(src) : "memory");
}
__device__ __forceinline__ void cpa_commit() {
    asm volatile("cp.async.commit_group;" ::: "memory");
}
template <int N> __device__ __forceinline__ void cpa_wait() {
    asm volatile("cp.async.wait_group %0;" :: "n"(N) : "memory");
}

// ---------------------------------------------------------------------------
// Prep (R11 exact): pack_mask + conv_all (2 launches)
// ---------------------------------------------------------------------------
__global__ __launch_bounds__(256) void pack_mask(const int* __restrict__ mask,
                                                 uint32_t* __restrict__ mw)
{
    const size_t w = (size_t)blockIdx.x * 256 + threadIdx.x;
    const int4* p = (const int4*)(mask + w * 32);
    uint32_t bits = 0;
#pragma unroll
    for (int i = 0; i < 8; i++) {
        int4 v = p[i];
        bits |= (v.x != 0 ? 1u : 0u) << (i * 4 + 0);
        bits |= (v.y != 0 ? 1u : 0u) << (i * 4 + 1);
        bits |= (v.z != 0 ? 1u : 0u) << (i * 4 + 2);
        bits |= (v.w != 0 ? 1u : 0u) << (i * 4 + 3);
    }
    mw[w] = bits;
}

__global__ __launch_bounds__(256) void conv_all(
    const float* __restrict__ syn,
    const float* __restrict__ q, const float* __restrict__ k, const float* __restrict__ v,
    const float* __restrict__ wq, const float* __restrict__ wk,
    const float* __restrict__ wv, const float* __restrict__ wo,
    const float* __restrict__ alpha_param,
    __half* __restrict__ osyn,
    __half* __restrict__ oq, __half* __restrict__ ok, __half* __restrict__ ov,
    __half* __restrict__ owq, __half* __restrict__ owk,
    __half* __restrict__ owv, __half* __restrict__ owo)
{
    const int blk = blockIdx.x;
    const float* src;
    __half* dst;
    size_t off;
    bool scale = false;
    if (blk < 4096)       { src = syn; dst = osyn; off = (size_t)blk * 1024; scale = true; }
    else if (blk < 6144)  { src = q;   dst = oq;   off = (size_t)(blk - 4096) * 1024; }
    else if (blk < 8192)  { src = k;   dst = ok;   off = (size_t)(blk - 6144) * 1024; }
    else if (blk < 10240) { src = v;   dst = ov;   off = (size_t)(blk - 8192) * 1024; }
    else if (blk < 10496) { src = wq;  dst = owq;  off = (size_t)(blk - 10240) * 1024; }
    else if (blk < 10752) { src = wk;  dst = owk;  off = (size_t)(blk - 10496) * 1024; }
    else if (blk < 11008) { src = wv;  dst = owv;  off = (size_t)(blk - 10752) * 1024; }
    else                  { src = wo;  dst = owo;  off = (size_t)(blk - 11008) * 1024; }

    float mult = 1.0f;
    if (scale) {
        float alpha = 1.0f / (1.0f + __expf(-alpha_param[0]));
        mult = (1.0f - alpha) * 1.4426950408889634f;
    }

    const size_t base = off + threadIdx.x;
    float4 t[4];
#pragma unroll
    for (int j = 0; j < 4; j++) t[j] = *(const float4*)(src + (base + j * 256) * 4);
#pragma unroll
    for (int j = 0; j < 4; j++) {
        t[j].x *= mult; t[j].y *= mult; t[j].z *= mult; t[j].w *= mult;
        *(uint2*)(dst + (base + j * 256) * 4) = f4h(t[j]);
    }
}

// ---------------------------------------------------------------------------
// GEMM core (R11 exact): fp16 in, 4-stage cp.async, k32.
// ---------------------------------------------------------------------------
#define GSTRIDE 40
#define GSTAGE_H (128 * GSTRIDE)
#define GEMM_SMEM (4 * 2 * GSTAGE_H * 2)   // 81920 bytes

__device__ __forceinline__ void gemm_core(
    const __half* __restrict__ A, const __half* __restrict__ W,
    const float* __restrict__ bias, void* __restrict__ Cv, int head_layout,
    __half* smh, int bx, int by)
{
    const int tid  = threadIdx.x;
    const int lane = tid & 31;
    const int warp = tid >> 5;
    const int wm   = warp >> 2;
    const int wn   = warp & 3;
    const int lr   = lane >> 2;
    const int lc   = lane & 3;
    const int aRow = lane & 15;
    const int aK   = (lane >> 4) * 8;
    const int bRow16 = (lane >> 4) * 8 + (lane & 7);
    const int bCol   = ((lane >> 3) & 1) * 8;

    const int fr  = tid >> 2;
    const int fch = (tid & 3) * 8;

    const __half* Ab = A + (size_t)(by * 128) * DD;
    const __half* Wb = W + (size_t)(bx * 128) * DD;

    const uint32_t base = smem_u32(smh);
    uint32_t sA[4], sW[4];
#pragma unroll
    for (int s = 0; s < 4; s++) {
        sA[s] = base + (uint32_t)(s * 2 * GSTAGE_H) * 2;
        sW[s] = base + (uint32_t)((s * 2 + 1) * GSTAGE_H) * 2;
    }
    const uint32_t d0 = (uint32_t)(fr * GSTRIDE + fch) * 2;
    const uint32_t d1 = (uint32_t)((fr + 64) * GSTRIDE + fch) * 2;

    float acc[4][4][4];
#pragma unroll
    for (int mt = 0; mt < 4; mt++)
#pragma unroll
        for (int nt = 0; nt < 4; nt++)
#pragma unroll
            for (int r = 0; r < 4; r++) acc[mt][nt][r] = 0.0f;

#define ISSUE(slice) { \
        int s_ = (slice) & 3; \
        cpa16(sA[s_] + d0, Ab + (size_t)fr        * DD + (slice) * 32 + fch); \
        cpa16(sA[s_] + d1, Ab + (size_t)(fr + 64) * DD + (slice) * 32 + fch); \
        cpa16(sW[s_] + d0, Wb + (size_t)fr        * DD + (slice) * 32 + fch); \
        cpa16(sW[s_] + d1, Wb + (size_t)(fr + 64) * DD + (slice) * 32 + fch); \
        cpa_commit(); }

    ISSUE(0);
    ISSUE(1);
    ISSUE(2);

    for (int kt = 0; kt < 32; kt++) {
        if (kt <= 29)      cpa_wait<2>();
        else if (kt == 30) cpa_wait<1>();
        else               cpa_wait<0>();
        __syncthreads();
        if (kt + 3 < 32) ISSUE(kt + 3);

        const int s = kt & 3;
#pragma unroll
        for (int ks = 0; ks < 2; ks++) {
            uint32_t af[4][4], bf[4][2];
#pragma unroll
            for (int mt = 0; mt < 4; mt++)
                ldsm_x4(af[mt], sA[s] +
                        ((uint32_t)((wm * 64 + mt * 16 + aRow) * GSTRIDE + ks * 16 + aK) << 1));
#pragma unroll
            for (int p = 0; p < 2; p++) {
                uint32_t t4[4];
                ldsm_x4(t4, sW[s] +
                        ((uint32_t)((wn * 32 + p * 16 + bRow16) * GSTRIDE + ks * 16 + bCol) << 1));
                bf[p * 2][0] = t4[0]; bf[p * 2][1] = t4[1];
                bf[p * 2 + 1][0] = t4[2]; bf[p * 2 + 1][1] = t4[3];
            }
#pragma unroll
            for (int mt = 0; mt < 4; mt++)
#pragma unroll
                for (int nt = 0; nt < 4; nt++)
                    mma16(acc[mt][nt], af[mt], bf[nt]);
        }
    }
#undef ISSUE

#pragma unroll
    for (int mt = 0; mt < 4; mt++) {
#pragma unroll
        for (int nt = 0; nt < 4; nt++) {
            int m0 = by * 128 + wm * 64 + mt * 16 + lr;
            int n0 = bx * 128 + wn * 32 + nt * 8 + 2 * lc;
            float bxv = bias[n0], byv = bias[n0 + 1];
            float v00 = acc[mt][nt][0] + bxv, v01 = acc[mt][nt][1] + byv;
            float v10 = acc[mt][nt][2] + bxv, v11 = acc[mt][nt][3] + byv;
            if (head_layout) {
                __half* C = (__half*)Cv;
                int hI = n0 >> 6, hd = n0 & 63;
                int bI0 = m0 >> 10, sI0 = m0 & 1023;
                int m1 = m0 + 8;
                int bI1 = m1 >> 10, sI1 = m1 & 1023;
                *(uint32_t*)(C + (((size_t)(bI0 * HH + hI) * SS + sI0) * HD + hd)) = f2h2(v00, v01);
                *(uint32_t*)(C + (((size_t)(bI1 * HH + hI) * SS + sI1) * HD + hd)) = f2h2(v10, v11);
            } else {
                float* C = (float*)Cv;
                *(float2*)(C + (size_t)m0 * DD + n0) = make_float2(v00, v01);
                *(float2*)(C + (size_t)(m0 + 8) * DD + n0) = make_float2(v10, v11);
            }
        }
    }
}

__global__ __launch_bounds__(256, 2) void gemm_qkv(
    const __half* __restrict__ qin, const __half* __restrict__ kin,
    const __half* __restrict__ vin,
    const __half* __restrict__ wq, const __half* __restrict__ wk,
    const __half* __restrict__ wv,
    const float* __restrict__ bq, const float* __restrict__ bk,
    const float* __restrict__ bv,
    __half* __restrict__ oq, __half* __restrict__ ok, __half* __restrict__ ov)
{
    extern __shared__ __align__(16) __half smh[];
    const int z = blockIdx.z;
    const __half* A = (z == 0) ? qin : (z == 1) ? kin : vin;
    const __half* W = (z == 0) ? wq  : (z == 1) ? wk  : wv;
    const float* bias = (z == 0) ? bq : (z == 1) ? bk : bv;
    __half* C = (z == 0) ? oq : (z == 1) ? ok : ov;
    gemm_core(A, W, bias, C, 1, smh, blockIdx.x, blockIdx.y);
}

__global__ __launch_bounds__(256, 2) void gemm_o(
    const __half* __restrict__ A, const __half* __restrict__ W,
    const float* __restrict__ bias, float* __restrict__ C)
{
    extern __shared__ __align__(16) __half smh[];
    gemm_core(A, W, bias, C, 0, smh, blockIdx.x, blockIdx.y);
}

// ---------------------------------------------------------------------------
// Flash attention (R11 structure; KV tile-0 cp.async issued BEFORE Q staging,
// Q staged through Ks1+Vs1 so the first tile's latency hides under Q setup)
// ---------------------------------------------------------------------------
__global__ __launch_bounds__(256, 2) void attn_f16(
    const __half* __restrict__ gq, const __half* __restrict__ gk,
    const __half* __restrict__ gv, const uint32_t* __restrict__ maskw,
    const __half* __restrict__ synh, const float* __restrict__ alpha_param,
    __half* __restrict__ out)
{
    __shared__ __align__(16) __half KV[4][64 * 72];
    const uint32_t KsA[2] = { smem_u32(KV[0]), smem_u32(KV[1]) };
    const uint32_t VsA[2] = { smem_u32(KV[2]), smem_u32(KV[3]) };

    const int tid  = threadIdx.x;
    const int lane = tid & 31;
    const int warp = tid >> 5;
    const int lr   = lane >> 2;
    const int lc   = lane & 3;
    const int aRow = lane & 15;
    const int aK   = (lane >> 4) * 8;
    const int bRow16 = (lane >> 4) * 8 + (lane & 7);
    const int bCol   = ((lane >> 3) & 1) * 8;
    const int vRow   = ((lane >> 3) & 1) * 8 + (lane & 7);
    const int vColH  = (lane >> 4) * 8;
    const int b = blockIdx.y >> 4;
    const int h = blockIdx.y & 15;
    const int qbase = blockIdx.x * 128;
    const int rb = warp * 16;

    const float alpha = 1.0f / (1.0f + __expf(-alpha_param[0]));
    const float sA2   = alpha * 0.125f * 1.4426950408889634f;

    const __half* qptr = gq + ((size_t)(b * HH + h) * SS + qbase) * HD;
    const __half* kptr = gk + (size_t)(b * HH + h) * SS * HD;
    const __half* vptr = gv + (size_t)(b * HH + h) * SS * HD;

    const int c0 = tid * 2;
    const int fr0 = c0 >> 3, fc0 = (c0 & 7) * 8;
    const int fr1 = (c0 + 1) >> 3, fc1 = ((c0 + 1) & 7) * 8;

#define ISSUE_KV(i, buf) { \
        const __half* kp_ = kptr + (size_t)(i) * 64 * HD; \
        const __half* vp_ = vptr + (size_t)(i) * 64 * HD; \
        cpa16(KsA[buf] + (uint32_t)(fr0 * 72 + fc0) * 2, kp_ + (size_t)fr0 * HD + fc0); \
        cpa16(KsA[buf] + (uint32_t)(fr1 * 72 + fc1) * 2, kp_ + (size_t)fr1 * HD + fc1); \
        cpa16(VsA[buf] + (uint32_t)(fr0 * 72 + fc0) * 2, vp_ + (size_t)fr0 * HD + fc0); \
        cpa16(VsA[buf] + (uint32_t)(fr1 * 72 + fc1) * 2, vp_ + (size_t)fr1 * HD + fc1); \
        cpa_commit(); }

    // Issue KV tile 0 FIRST (into Ks0/Vs0); its latency hides under Q staging.
    ISSUE_KV(0, 0);

    // Stage Q (128x64): rows 0..63 -> Ks1 (KV[1]), rows 64..127 -> Vs1 (KV[3]).
    {
#pragma unroll
        for (int i = 0; i < 8; i++) {
            int id = tid + i * 256;
            int r  = id >> 4;
            int c4 = (id & 15) * 4;
            __half* dst = (r < 64) ? &KV[1][r * 72 + c4] : &KV[3][(r - 64) * 72 + c4];
            *(uint2*)dst = *(const uint2*)(qptr + (size_t)r * HD + c4);
        }
    }
    __syncthreads();

    uint32_t qf[4][4];
    {
        const uint32_t qsBase = (warp < 4) ? KsA[1] : VsA[1];
        const int qrow = (warp < 4) ? rb : (rb - 64);
#pragma unroll
        for (int kk = 0; kk < 4; kk++)
            ldsm_x4(qf[kk], qsBase + ((uint32_t)((qrow + aRow) * 72 + kk * 16 + aK) << 1));
    }
    __syncthreads();

    float O[8][4];
#pragma unroll
    for (int nt = 0; nt < 8; nt++)
#pragma unroll
        for (int r = 0; r < 4; r++) O[nt][r] = 0.0f;
    float m0r = -INFINITY, m1r = -INFINITY, l0 = 0.0f, l1 = 0.0f;

    const int qr0 = qbase + rb + lr;
    const int qr1 = qr0 + 8;
    const uint32_t* mw0 = maskw + ((size_t)b * SS + qr0) * 32;
    const uint32_t* mw1 = maskw + ((size_t)b * SS + qr1) * 32;
    const __half* sy0p = synh + ((size_t)h * SS + qr0) * SS;
    const __half* sy1p = synh + ((size_t)h * SS + qr1) * SS;

    int buf = 0;
    for (int it = 0; it < 16; it++) {
        const int kb = it * 64;
        cpa_wait<0>();
        __syncthreads();
        if (it < 15) ISSUE_KV(it + 1, buf ^ 1);

        float sacc[8][4];
#pragma unroll
        for (int nt = 0; nt < 8; nt++)
            sacc[nt][0] = sacc[nt][1] = sacc[nt][2] = sacc[nt][3] = 0.0f;
#pragma unroll
        for (int p = 0; p < 4; p++) {
#pragma unroll
            for (int kk = 0; kk < 4; kk++) {
                uint32_t t4[4];
                ldsm_x4(t4, KsA[buf] +
                        ((uint32_t)((p * 16 + bRow16) * 72 + kk * 16 + bCol) << 1));
                mma16(sacc[p * 2],     qf[kk], t4);
                mma16(sacc[p * 2 + 1], qf[kk], t4 + 2);
            }
        }

        const uint32_t w0a = mw0[kb >> 5], w0b = mw0[(kb >> 5) + 1];
        const uint32_t w1a = mw1[kb >> 5], w1b = mw1[(kb >> 5) + 1];
        float mx0 = -INFINITY, mx1 = -INFINITY;
#pragma unroll
        for (int nt = 0; nt < 8; nt++) {
            const int pos = nt * 8 + 2 * lc;
            const int sh  = pos & 31;
            const uint32_t wr0 = (nt < 4) ? w0a : w0b;
            const uint32_t wr1 = (nt < 4) ? w1a : w1b;
            float2 sy0 = __half22float2(*(const __half2*)(sy0p + kb + pos));
            float2 sy1 = __half22float2(*(const __half2*)(sy1p + kb + pos));
            sacc[nt][0] = ((wr0 >> sh) & 1u)       ? fmaf(sacc[nt][0], sA2, sy0.x) : -1.0e9f;
            sacc[nt][1] = ((wr0 >> (sh + 1)) & 1u) ? fmaf(sacc[nt][1], sA2, sy0.y) : -1.0e9f;
            sacc[nt][2] = ((wr1 >> sh) & 1u)       ? fmaf(sacc[nt][2], sA2, sy1.x) : -1.0e9f;
            sacc[nt][3] = ((wr1 >> (sh + 1)) & 1u) ? fmaf(sacc[nt][3], sA2, sy1.y) : -1.0e9f;
            mx0 = fmaxf(mx0, fmaxf(sacc[nt][0], sacc[nt][1]));
            mx1 = fmaxf(mx1, fmaxf(sacc[nt][2], sacc[nt][3]));
        }
        mx0 = fmaxf(mx0, __shfl_xor_sync(0xffffffffu, mx0, 1));
        mx0 = fmaxf(mx0, __shfl_xor_sync(0xffffffffu, mx0, 2));
        mx1 = fmaxf(mx1, __shfl_xor_sync(0xffffffffu, mx1, 1));
        mx1 = fmaxf(mx1, __shfl_xor_sync(0xffffffffu, mx1, 2));

        float mn0 = fmaxf(m0r, mx0), mn1 = fmaxf(m1r, mx1);
        float sc0 = exp2f(m0r - mn0), sc1 = exp2f(m1r - mn1);
        m0r = mn0; m1r = mn1;

        uint32_t pf[4][4];
        float rs0 = 0.0f, rs1 = 0.0f;
#pragma unroll
        for (int nt = 0; nt < 8; nt++) {
            float p0 = exp2f(sacc[nt][0] - mn0);
            float p1 = exp2f(sacc[nt][1] - mn0);
            float p2 = exp2f(sacc[nt][2] - mn1);
            float p3 = exp2f(sacc[nt][3] - mn1);
            rs0 += p0 + p1;
            rs1 += p2 + p3;
            pf[nt >> 1][(nt & 1) * 2 + 0] = f2h2(p0, p1);
            pf[nt >> 1][(nt & 1) * 2 + 1] = f2h2(p2, p3);
        }
        rs0 += __shfl_xor_sync(0xffffffffu, rs0, 1);
        rs0 += __shfl_xor_sync(0xffffffffu, rs0, 2);
        rs1 += __shfl_xor_sync(0xffffffffu, rs1, 1);
        rs1 += __shfl_xor_sync(0xffffffffu, rs1, 2);
        l0 = l0 * sc0 + rs0;
        l1 = l1 * sc1 + rs1;

#pragma unroll
        for (int nt = 0; nt < 8; nt++) {
            O[nt][0] *= sc0; O[nt][1] *= sc0;
            O[nt][2] *= sc1; O[nt][3] *= sc1;
        }

#pragma unroll
        for (int j = 0; j < 4; j++) {
#pragma unroll
            for (int p = 0; p < 4; p++) {
                uint32_t t4[4];
                ldsm_x4t(t4, VsA[buf] +
                         ((uint32_t)((j * 16 + vRow) * 72 + p * 16 + vColH) << 1));
                mma16(O[p * 2],     pf[j], t4);
                mma16(O[p * 2 + 1], pf[j], t4 + 2);
            }
        }

        buf ^= 1;
    }
#undef ISSUE_KV

    float inv0 = 1.0f / l0, inv1 = 1.0f / l1;
    __half* o0 = out + ((size_t)b * SS + qr0) * DD + h * HD;
    __half* o1 = out + ((size_t)b * SS + qr1) * DD + h * HD;
#pragma unroll
    for (int nt = 0; nt < 8; nt++) {
        int c = nt * 8 + 2 * lc;
        *(uint32_t*)(o0 + c) = f2h2(O[nt][0] * inv0, O[nt][1] * inv0);
        *(uint32_t*)(o1 + c) = f2h2(O[nt][2] * inv1, O[nt][3] * inv1);
    }
}

// ---------------------------------------------------------------------------
extern "C" void kernel_launch(void* const* d_in, const int* in_sizes, int n_in,
                              void* d_out, int out_size)
{
    const float* query  = (const float*)d_in[0];
    const float* key_in = (const float*)d_in[1];
    const float* value  = (const float*)d_in[2];
    const int*   mask   = (const int*)d_in[3];
    const float* Wq = (const float*)d_in[4];
    const float* bq = (const float*)d_in[5];
    const float* Wk = (const float*)d_in[6];
    const float* bk = (const float*)d_in[7];
    const float* Wv = (const float*)d_in[8];
    const float* bv = (const float*)d_in[9];
    const float* Wo = (const float*)d_in[10];
    const float* bo = (const float*)d_in[11];
    const float* syn = (const float*)d_in[12];
    const float* alpha_param = (const float*)d_in[13];
    float* out = (float*)d_out;

    __half *pq, *pk, *pv, *paoh, *psynh, *pqin, *pkin, *pvin, *pwq, *pwk, *pwv, *pwo;
    uint32_t *pmw;
    cudaGetSymbolAddress((void**)&pq, g_q);
    cudaGetSymbolAddress((void**)&pk, g_k);
    cudaGetSymbolAddress((void**)&pv, g_v);
    cudaGetSymbolAddress((void**)&paoh, g_aoh);
    cudaGetSymbolAddress((void**)&pmw, g_maskw);
    cudaGetSymbolAddress((void**)&psynh, g_synh);
    cudaGetSymbolAddress((void**)&pqin, g_qin);
    cudaGetSymbolAddress((void**)&pkin, g_kin);
    cudaGetSymbolAddress((void**)&pvin, g_vin);
    cudaGetSymbolAddress((void**)&pwq, g_wq);
    cudaGetSymbolAddress((void**)&pwk, g_wk);
    cudaGetSymbolAddress((void**)&pwv, g_wv);
    cudaGetSymbolAddress((void**)&pwo, g_wo);

    // Prep: 2 launches (R11 exact)
    pack_mask<<<(BB * SS * (SS / 32)) / 256, 256>>>(mask, pmw);
    conv_all<<<11264, 256>>>(syn, query, key_in, value, Wq, Wk, Wv, Wo,
                             alpha_param,
                             psynh, pqin, pkin, pvin, pwq, pwk, pwv, pwo);

    cudaFuncSetAttribute(gemm_qkv,
                         cudaFuncAttributeMaxDynamicSharedMemorySize, GEMM_SMEM);
    cudaFuncSetAttribute(gemm_o,
                         cudaFuncAttributeMaxDynamicSharedMemorySize, GEMM_SMEM);

    gemm_qkv<<<dim3(DD / 128, (BB * SS) / 128, 3), 256, GEMM_SMEM>>>(
        pqin, pkin, pvin, pwq, pwk, pwv, bq, bk, bv, pq, pk, pv);

    attn_f16<<<dim3(SS / 128, BB * HH), 256>>>(
        pq, pk, pv, pmw, psynh, alpha_param, paoh);

    gemm_o<<<dim3(DD / 128, (BB * SS) / 128), 256, GEMM_SMEM>>>(
        paoh, pwo, bo, out);
}